// round 15
// baseline (speedup 1.0000x reference)
#include <cuda_runtime.h>
#include <cuda_bf16.h>
#include <cstddef>
#include <cstdint>

#define H       128
#define NPL     100000
#define NTR     200000
#define NAR     50000
#define NT      350000
#define OFF_TR  100000
#define OFF_AR  300000
#define EPT     500000
#define ETA     200000
#define LBL     100000
#define GRID    152
#define NDIR    (2 * (EPT + ETA))

// ---------------- scratch: bf16 hi/lo feature planes ----------------
__device__ __nv_bfloat16 g_xh[(size_t)NT * H];
__device__ __nv_bfloat16 g_xl[(size_t)NT * H];
__device__ __nv_bfloat16 g_yh[(size_t)NT * H];
__device__ __nv_bfloat16 g_yl[(size_t)NT * H];
__device__ __nv_bfloat16 g_ah[(size_t)NT * H];
__device__ __nv_bfloat16 g_al[(size_t)NT * H];
__device__ __align__(16) __nv_bfloat16 g_zrow[64];   // zeros (OOB cp.async src)
__device__ float g_inv[NT];
__device__ int   g_deg[NT];
__device__ int   g_rowptr[NT];
__device__ int   g_cur[NT];
__device__ int   g_adj[NDIR];
__device__ int   g_gctr;

// ---------------- generic helpers ----------------
__device__ __forceinline__ uint32_t smem_u32(const void* p) {
    uint32_t a;
    asm("{ .reg .u64 t; cvta.to.shared.u64 t, %1; cvt.u32.u64 %0, t; }" : "=r"(a) : "l"(p));
    return a;
}
#define SWZ(o) ((o) ^ (((o) >> 3) & 0x70))

__device__ __forceinline__ void cp16(void* smem_dst, const void* gsrc) {
    unsigned ds = (unsigned)__cvta_generic_to_shared(smem_dst);
    asm volatile("cp.async.cg.shared.global [%0], [%1], 16;" :: "r"(ds), "l"(gsrc) : "memory");
}

// pack two fp32 -> bf16x2 (truncation hi / residual lo)
__device__ __forceinline__ uint32_t pack_hi(float a, float b) {
    return __byte_perm(__float_as_uint(a), __float_as_uint(b), 0x7632);
}
__device__ __forceinline__ uint32_t pack_lo(float a, float b) {
    float ra = a - __uint_as_float(__float_as_uint(a) & 0xFFFF0000u);
    float rb = b - __uint_as_float(__float_as_uint(b) & 0xFFFF0000u);
    return __byte_perm(__float_as_uint(ra), __float_as_uint(rb), 0x7632);
}

// ---------------- mma.sync helpers ----------------
__device__ __forceinline__ void ldsm4(uint32_t& r0, uint32_t& r1, uint32_t& r2,
                                      uint32_t& r3, uint32_t addr) {
    asm volatile("ldmatrix.sync.aligned.m8n8.x4.shared.b16 {%0,%1,%2,%3}, [%4];"
                 : "=r"(r0), "=r"(r1), "=r"(r2), "=r"(r3) : "r"(addr));
}
__device__ __forceinline__ void mma16816(float* c, const uint32_t* a,
                                         uint32_t b0, uint32_t b1) {
    asm volatile(
        "mma.sync.aligned.m16n8k16.row.col.f32.bf16.bf16.f32 "
        "{%0,%1,%2,%3}, {%4,%5,%6,%7}, {%8,%9}, {%0,%1,%2,%3};"
        : "+f"(c[0]), "+f"(c[1]), "+f"(c[2]), "+f"(c[3])
        : "r"(a[0]), "r"(a[1]), "r"(a[2]), "r"(a[3]), "r"(b0), "r"(b1));
}

// fast truncation split: 16 fp32 -> 8 packed hi u32 + 8 packed lo u32
__device__ __forceinline__ void fsplit16(const float* f, uint32_t* hi, uint32_t* lo) {
    #pragma unroll
    for (int j = 0; j < 8; j++) {
        hi[j] = pack_hi(f[2 * j], f[2 * j + 1]);
        lo[j] = pack_lo(f[2 * j], f[2 * j + 1]);
    }
}

// ---------------- small kernels ----------------
__global__ void k_embed2(const int* __restrict__ pl, const int* __restrict__ ar,
                         const float* __restrict__ plt, const float* __restrict__ art,
                         const float* __restrict__ tt,
                         __nv_bfloat16* __restrict__ xh, __nv_bfloat16* __restrict__ xl)
{
    int t = blockIdx.x * blockDim.x + threadIdx.x;
    int node; float4 v;
    if (t < NPL * 32) {
        int i = t >> 5, c = t & 31;
        v = ((const float4*)(plt + (size_t)pl[i] * H))[c];
        float4 tv = ((const float4*)tt)[c];
        v.x += tv.x; v.y += tv.y; v.z += tv.z; v.w += tv.w;
        node = i;
        size_t off = (size_t)node * H + (c << 2);
        *(uint2*)(xh + off) = make_uint2(pack_hi(v.x, v.y), pack_hi(v.z, v.w));
        *(uint2*)(xl + off) = make_uint2(pack_lo(v.x, v.y), pack_lo(v.z, v.w));
    } else {
        t -= NPL * 32;
        if (t >= NAR * 32) return;
        int i = t >> 5, c = t & 31;
        v = ((const float4*)(art + (size_t)ar[i] * H))[c];
        float4 tv = ((const float4*)(tt + 2 * H))[c];
        v.x += tv.x; v.y += tv.y; v.z += tv.z; v.w += tv.w;
        node = OFF_AR + i;
        size_t off = (size_t)node * H + (c << 2);
        *(uint2*)(xh + off) = make_uint2(pack_hi(v.x, v.y), pack_hi(v.z, v.w));
        *(uint2*)(xl + off) = make_uint2(pack_lo(v.x, v.y), pack_lo(v.z, v.w));
    }
}

__global__ void k_deg(const int* __restrict__ sp, const int* __restrict__ dp,
                      const int* __restrict__ st, const int* __restrict__ dt)
{
    int e = blockIdx.x * blockDim.x + threadIdx.x;
    if (e == 0) g_gctr = 0;
    if (e < EPT) {
        atomicAdd(&g_deg[dp[e] + OFF_TR], 1);
        atomicAdd(&g_deg[sp[e]], 1);
    } else if (e < EPT + ETA) {
        int i = e - EPT;
        atomicAdd(&g_deg[dt[i] + OFF_AR], 1);
        atomicAdd(&g_deg[st[i] + OFF_TR], 1);
    }
}

__global__ void k_alloc()
{
    int i = blockIdx.x * blockDim.x + threadIdx.x;
    if (i < NT) {
        int d = g_deg[i];
        g_rowptr[i] = atomicAdd(&g_gctr, d);
        g_cur[i] = 0;
        g_inv[i] = 1.0f / fmaxf((float)d, 1.0f);
    }
}

__global__ void k_fill(const int* __restrict__ sp, const int* __restrict__ dp,
                       const int* __restrict__ st, const int* __restrict__ dt)
{
    int e = blockIdx.x * blockDim.x + threadIdx.x;
    int a, b;
    if (e < EPT) { a = sp[e];          b = dp[e] + OFF_TR; }
    else if (e < EPT + ETA) { int i = e - EPT; a = st[i] + OFF_TR; b = dt[i] + OFF_AR; }
    else return;
    int pa = atomicAdd(&g_cur[a], 1);
    g_adj[g_rowptr[a] + pa] = b;
    int pb = atomicAdd(&g_cur[b], 1);
    g_adj[g_rowptr[b] + pb] = a;
}

// CSR mean-gather over bf16 planes: warp per node; lane owns 4 elems; 4-way MLP
__global__ void k_gather(const __nv_bfloat16* __restrict__ srch,
                         const __nv_bfloat16* __restrict__ srcl,
                         __nv_bfloat16* __restrict__ dsth,
                         __nv_bfloat16* __restrict__ dstl)
{
    int node = blockIdx.x * 8 + (threadIdx.x >> 5);
    if (node >= NT) return;
    int lane = threadIdx.x & 31;
    const int beg = g_rowptr[node];
    const int d   = g_deg[node];
    const int eo  = lane * 4;
    float a0 = 0.f, a1 = 0.f, a2 = 0.f, a3 = 0.f;

    auto accum = [&](int s) {
        size_t off = (size_t)s * H + eo;
        uint2 h = *(const uint2*)(srch + off);
        uint2 l = *(const uint2*)(srcl + off);
        float2 h0 = __bfloat1622float2(*(__nv_bfloat162*)&h.x);
        float2 h1 = __bfloat1622float2(*(__nv_bfloat162*)&h.y);
        float2 l0 = __bfloat1622float2(*(__nv_bfloat162*)&l.x);
        float2 l1 = __bfloat1622float2(*(__nv_bfloat162*)&l.y);
        a0 += h0.x + l0.x; a1 += h0.y + l0.y;
        a2 += h1.x + l1.x; a3 += h1.y + l1.y;
    };

    int j = 0;
    for (; j + 4 <= d; j += 4) {
        int s0 = g_adj[beg + j + 0];
        int s1 = g_adj[beg + j + 1];
        int s2 = g_adj[beg + j + 2];
        int s3 = g_adj[beg + j + 3];
        accum(s0); accum(s1); accum(s2); accum(s3);
    }
    for (; j < d; j++) accum(g_adj[beg + j]);

    float iv = g_inv[node];
    a0 *= iv; a1 *= iv; a2 *= iv; a3 *= iv;
    size_t off = (size_t)node * H + eo;
    *(uint2*)(dsth + off) = make_uint2(pack_hi(a0, a1), pack_hi(a2, a3));
    *(uint2*)(dstl + off) = make_uint2(pack_lo(a0, a1), pack_lo(a2, a3));
}

// ---------------- split-bf16 mma.sync GEMM over feature planes ----------------
// out = act( concatK(AP, BP) @ Wcat^T + bias ), K = 64*NCH.
// Tile 128x128; 16 warps 4x4; warp 32x32; s-outer fragment reuse (R13).
// Plane mode: A chunks copied hi/lo bf16 -> smem by cp.async (no fsplit/STS in
// loop); schedule per chunk: wait_group 0; sync; issue(c+1); compute(c).
// SRCF32 mode (encode): fp32 LDG + fsplit + STS pipeline (R13 path).
// Epilogue writes split planes (outh/outl) or fp32 logits (DOT).
template<int KK, bool DUALW, bool RELU, bool GATHER, bool DOT, bool SRCF32>
__global__ void __launch_bounds__(512, 1) k_mma(
    const float* __restrict__ A32,
    const __nv_bfloat16* __restrict__ APh, const __nv_bfloat16* __restrict__ APl,
    const __nv_bfloat16* __restrict__ BPh, const __nv_bfloat16* __restrict__ BPl,
    const float* __restrict__ W1, const float* __restrict__ W2,
    const float* __restrict__ b1, const float* __restrict__ b2,
    const int* __restrict__ lrow, const int* __restrict__ lcol,
    const float* __restrict__ wp2, const float* __restrict__ bp2,
    __nv_bfloat16* __restrict__ outh, __nv_bfloat16* __restrict__ outl,
    float* __restrict__ outf, int n)
{
    extern __shared__ char smraw[];
    const uint32_t raw  = smem_u32(smraw);
    const uint32_t base = (raw + 1023) & ~1023u;
    char* sb = smraw + (base - raw);

    constexpr int NCH = KK / 64;
    constexpr uint32_t AOFF = (uint32_t)NCH * 2 * 16384;
    constexpr uint32_t SOFF = AOFF + 2 * 32768;

    float* bs   = (float*)(sb + SOFF);
    float* w2s  = bs + 128;
    float* lsum = w2s + 128;

    const int tid = threadIdx.x;
    const int wid = tid >> 5, lane = tid & 31;

    // ---- stage W (hi/lo split, SW128 tiles), once per block ----
    for (int idx = tid; idx < 8 * KK; idx += 512) {
        int row = idx / (KK / 16);
        int kglob = (idx % (KK / 16)) * 16;
        const float* src;
        if (DUALW) src = (kglob < 128) ? (W1 + (size_t)row * 128 + kglob)
                                       : (W2 + (size_t)row * 128 + (kglob - 128));
        else       src = W1 + (size_t)row * KK + kglob;
        float f[16];
        *(float4*)(f + 0)  = ((const float4*)src)[0];
        *(float4*)(f + 4)  = ((const float4*)src)[1];
        *(float4*)(f + 8)  = ((const float4*)src)[2];
        *(float4*)(f + 12) = ((const float4*)src)[3];
        uint32_t hi[8], lo[8];
        fsplit16(f, hi, lo);
        int chunk = kglob >> 6;
        int kb = (kglob & 63) * 2;
        char* th = sb + (chunk * 2 + 0) * 16384;
        char* tl = sb + (chunk * 2 + 1) * 16384;
        uint32_t o0 = SWZ((uint32_t)(row * 128 + kb));
        uint32_t o1 = SWZ((uint32_t)(row * 128 + kb + 16));
        *(uint4*)(th + o0) = make_uint4(hi[0], hi[1], hi[2], hi[3]);
        *(uint4*)(th + o1) = make_uint4(hi[4], hi[5], hi[6], hi[7]);
        *(uint4*)(tl + o0) = make_uint4(lo[0], lo[1], lo[2], lo[3]);
        *(uint4*)(tl + o1) = make_uint4(lo[4], lo[5], lo[6], lo[7]);
    }
    for (int j = tid; j < 128; j += 512) {
        bs[j] = b1[j] + (b2 ? b2[j] : 0.0f);
        if (DOT) w2s[j] = wp2[j];
    }
    __syncthreads();

    const int wr = wid >> 2, wc = wid & 3;
    const uint32_t rowA  = (uint32_t)(lane & 15);
    const uint32_t kselA = (uint32_t)((lane >> 4) * 16);
    const uint32_t rowB  = (uint32_t)(((lane >> 4) * 8) + (lane & 7));
    const uint32_t kselB = (uint32_t)(((lane >> 3) & 1) * 16);
    const int srow = tid >> 2, sp4 = tid & 3;
    const int skg = sp4;   // SRCF32 path naming

    const int ntiles = (n + 127) >> 7;

    // ---- SRCF32 staging lambdas (encode) ----
    auto ldreg = [&](int n0, int ch, float* f) {
        #pragma unroll
        for (int q = 0; q < 16; q++) f[q] = 0.f;
        int gn = n0 + srow;
        if (gn < n) {
            const float* src = A32 + (size_t)gn * KK + ch * 64 + skg * 16;
            *(float4*)(f + 0)  = ((const float4*)src)[0];
            *(float4*)(f + 4)  = ((const float4*)src)[1];
            *(float4*)(f + 8)  = ((const float4*)src)[2];
            *(float4*)(f + 12) = ((const float4*)src)[3];
        }
    };
    auto stchunk = [&](int buf, const float* f) {
        uint32_t hi[8], lo[8];
        fsplit16(f, hi, lo);
        char* dst = sb + AOFF + (uint32_t)buf * 32768;
        uint32_t o0 = SWZ((uint32_t)(srow * 128 + skg * 32));
        uint32_t o1 = SWZ((uint32_t)(srow * 128 + skg * 32 + 16));
        *(uint4*)(dst + o0) = make_uint4(hi[0], hi[1], hi[2], hi[3]);
        *(uint4*)(dst + o1) = make_uint4(hi[4], hi[5], hi[6], hi[7]);
        *(uint4*)(dst + 16384 + o0) = make_uint4(lo[0], lo[1], lo[2], lo[3]);
        *(uint4*)(dst + 16384 + o1) = make_uint4(lo[4], lo[5], lo[6], lo[7]);
    };
    // ---- plane staging via cp.async ----
    auto issue = [&](int n0, int c) {
        if (c < NCH) {
            char* dst = sb + AOFF + (uint32_t)(c & 1) * 32768;
            int gn = n0 + srow;
            const __nv_bfloat16 *sh, *sl;
            if (gn < n) {
                if (GATHER) {
                    int r = (c < 2) ? lrow[gn] : (OFF_TR + lcol[gn]);
                    size_t off = (size_t)r * 128 + (c & 1) * 64;
                    sh = BPh + off; sl = BPl + off;
                } else {
                    const __nv_bfloat16* ph = (c < 2) ? APh : BPh;
                    const __nv_bfloat16* plo = (c < 2) ? APl : BPl;
                    size_t off = (size_t)gn * 128 + (c & 1) * 64;
                    sh = ph + off; sl = plo + off;
                }
            } else { sh = g_zrow; sl = g_zrow; }
            #pragma unroll
            for (int g = 0; g < 2; g++) {
                int seg = sp4 * 2 + g;
                uint32_t o = SWZ((uint32_t)(srow * 128 + seg * 16));
                cp16(dst + o,         sh + seg * 8);
                cp16(dst + 16384 + o, sl + seg * 8);
            }
        }
        asm volatile("cp.async.commit_group;" ::: "memory");
    };

    float acc[2][4][4];

    auto compute = [&](int c) {
        const uint32_t ahi = base + AOFF + (uint32_t)(c & 1) * 32768;
        const uint32_t alo = ahi + 16384;
        const uint32_t whi = base + (uint32_t)(c * 2) * 16384;
        const uint32_t wlo = whi + 16384;
        #pragma unroll
        for (int s = 0; s < 4; s++) {
            uint32_t ah[2][4], al[2][4];
            #pragma unroll
            for (int mt = 0; mt < 2; mt++) {
                uint32_t off = SWZ((uint32_t)((wr * 32 + mt * 16) + rowA) * 128
                                   + (uint32_t)(s * 32) + kselA);
                ldsm4(ah[mt][0], ah[mt][1], ah[mt][2], ah[mt][3], ahi + off);
                ldsm4(al[mt][0], al[mt][1], al[mt][2], al[mt][3], alo + off);
            }
            uint32_t bh[4][2], bl[4][2];
            #pragma unroll
            for (int bp = 0; bp < 2; bp++) {
                uint32_t off = SWZ((uint32_t)((wc * 32 + bp * 16) + rowB) * 128
                                   + (uint32_t)(s * 32) + kselB);
                uint32_t r0, r1, r2, r3;
                ldsm4(r0, r1, r2, r3, whi + off);
                bh[bp * 2][0] = r0;     bh[bp * 2][1] = r1;
                bh[bp * 2 + 1][0] = r2; bh[bp * 2 + 1][1] = r3;
                ldsm4(r0, r1, r2, r3, wlo + off);
                bl[bp * 2][0] = r0;     bl[bp * 2][1] = r1;
                bl[bp * 2 + 1][0] = r2; bl[bp * 2 + 1][1] = r3;
            }
            #pragma unroll
            for (int mt = 0; mt < 2; mt++)
                #pragma unroll
                for (int nt = 0; nt < 4; nt++) {
                    mma16816(acc[mt][nt], ah[mt], bh[nt][0], bh[nt][1]);
                    mma16816(acc[mt][nt], ah[mt], bl[nt][0], bl[nt][1]);
                    mma16816(acc[mt][nt], al[mt], bh[nt][0], bh[nt][1]);
                }
        }
    };

    for (int tile = blockIdx.x; tile < ntiles; tile += GRID) {
        const int n0 = tile << 7;

        #pragma unroll
        for (int mt = 0; mt < 2; mt++)
            #pragma unroll
            for (int nt = 0; nt < 4; nt++)
                #pragma unroll
                for (int q = 0; q < 4; q++) acc[mt][nt][q] = 0.f;
        if (DOT && tid < 128) lsum[tid] = 0.f;

        if (SRCF32) {
            {
                float f[16];
                ldreg(n0, 0, f);
                stchunk(0, f);
            }
            __syncthreads();
            #pragma unroll 1
            for (int c = 0; c < NCH; c++) {
                float f[16];
                if (c + 1 < NCH) ldreg(n0, c + 1, f);
                compute(c);
                if (c + 1 < NCH) stchunk((c + 1) & 1, f);
                __syncthreads();
            }
        } else {
            issue(n0, 0);
            #pragma unroll 1
            for (int c = 0; c < NCH; c++) {
                asm volatile("cp.async.wait_group 0;" ::: "memory");
                __syncthreads();
                issue(n0, c + 1);
                compute(c);
            }
        }

        // ---- epilogue ----
        const int lr = lane >> 2, lc2 = (lane & 3) * 2;
        if (DOT) {
            #pragma unroll
            for (int mt = 0; mt < 2; mt++) {
                float plo = 0.f, phi = 0.f;
                #pragma unroll
                for (int nt = 0; nt < 4; nt++) {
                    int col = wc * 32 + nt * 8 + lc2;
                    float w0 = w2s[col], w1 = w2s[col + 1];
                    float b0 = bs[col],  b1 = bs[col + 1];
                    plo += fmaxf(acc[mt][nt][0] + b0, 0.f) * w0
                         + fmaxf(acc[mt][nt][1] + b1, 0.f) * w1;
                    phi += fmaxf(acc[mt][nt][2] + b0, 0.f) * w0
                         + fmaxf(acc[mt][nt][3] + b1, 0.f) * w1;
                }
                plo += __shfl_xor_sync(0xffffffffu, plo, 1);
                plo += __shfl_xor_sync(0xffffffffu, plo, 2);
                phi += __shfl_xor_sync(0xffffffffu, phi, 1);
                phi += __shfl_xor_sync(0xffffffffu, phi, 2);
                if ((lane & 3) == 0) {
                    atomicAdd(&lsum[wr * 32 + mt * 16 + lr], plo);
                    atomicAdd(&lsum[wr * 32 + mt * 16 + lr + 8], phi);
                }
            }
            __syncthreads();
            if (tid < 128) {
                int gn = n0 + tid;
                if (gn < n) outf[gn] = lsum[tid] + bp2[0];
            }
            __syncthreads();
        } else {
            #pragma unroll
            for (int mt = 0; mt < 2; mt++) {
                int r0 = n0 + wr * 32 + mt * 16 + lr;
                int r1 = r0 + 8;
                #pragma unroll
                for (int nt = 0; nt < 4; nt++) {
                    int col = wc * 32 + nt * 8 + lc2;
                    float b0 = bs[col], b1 = bs[col + 1];
                    float v0 = acc[mt][nt][0] + b0, v1 = acc[mt][nt][1] + b1;
                    float v2 = acc[mt][nt][2] + b0, v3 = acc[mt][nt][3] + b1;
                    if (RELU) {
                        v0 = fmaxf(v0, 0.f); v1 = fmaxf(v1, 0.f);
                        v2 = fmaxf(v2, 0.f); v3 = fmaxf(v3, 0.f);
                    }
                    if (r0 < n) {
                        size_t off = (size_t)r0 * 128 + col;
                        *(uint32_t*)(outh + off) = pack_hi(v0, v1);
                        *(uint32_t*)(outl + off) = pack_lo(v0, v1);
                    }
                    if (r1 < n) {
                        size_t off = (size_t)r1 * 128 + col;
                        *(uint32_t*)(outh + off) = pack_hi(v2, v3);
                        *(uint32_t*)(outl + off) = pack_lo(v2, v3);
                    }
                }
            }
        }
    }
}

// ---------------- launch ----------------
extern "C" void kernel_launch(void* const* d_in, const int* in_sizes, int n_in,
                              void* d_out, int out_size)
{
    const int*   pl_ids   = (const int*)  d_in[0];
    const int*   ar_ids   = (const int*)  d_in[1];
    const float* track_x  = (const float*)d_in[2];
    const int*   src_pt   = (const int*)  d_in[3];
    const int*   dst_pt   = (const int*)  d_in[4];
    const int*   src_ta   = (const int*)  d_in[5];
    const int*   dst_ta   = (const int*)  d_in[6];
    const int*   lab_row  = (const int*)  d_in[7];
    const int*   lab_col  = (const int*)  d_in[8];
    const float* pl_table = (const float*)d_in[9];
    const float* ar_table = (const float*)d_in[10];
    const float* Wtr      = (const float*)d_in[11];
    const float* btr      = (const float*)d_in[12];
    const float* type_tab = (const float*)d_in[13];
    const float* Wl0      = (const float*)d_in[14];
    const float* bl0      = (const float*)d_in[15];
    const float* Wr0      = (const float*)d_in[16];
    const float* Wl1      = (const float*)d_in[17];
    const float* bl1      = (const float*)d_in[18];
    const float* Wr1      = (const float*)d_in[19];
    const float* Wp1      = (const float*)d_in[20];
    const float* bp1      = (const float*)d_in[21];
    const float* Wp2      = (const float*)d_in[22];
    const float* bp2      = (const float*)d_in[23];
    float* out = (float*)d_out;

    __nv_bfloat16 *xh, *xl, *yh, *yl, *ah, *al; int* deg;
    cudaGetSymbolAddress((void**)&xh, g_xh);
    cudaGetSymbolAddress((void**)&xl, g_xl);
    cudaGetSymbolAddress((void**)&yh, g_yh);
    cudaGetSymbolAddress((void**)&yl, g_yl);
    cudaGetSymbolAddress((void**)&ah, g_ah);
    cudaGetSymbolAddress((void**)&al, g_al);
    cudaGetSymbolAddress((void**)&deg, g_deg);

    const int SMEM_K256 = 1024 + 8 * 16384 + 2 * 32768 + 1536;   // 199168
    const int SMEM_K128 = 1024 + 4 * 16384 + 2 * 32768 + 1536;   // 133632

    cudaFuncSetAttribute(k_mma<128, false, false, false, false, true >, cudaFuncAttributeMaxDynamicSharedMemorySize, SMEM_K128);
    cudaFuncSetAttribute(k_mma<256, true,  true,  false, false, false>, cudaFuncAttributeMaxDynamicSharedMemorySize, SMEM_K256);
    cudaFuncSetAttribute(k_mma<256, false, true,  true,  true,  false>, cudaFuncAttributeMaxDynamicSharedMemorySize, SMEM_K256);

    // side stream: CSR build + pl/ar embeds (disjoint from encode's x region)
    cudaStream_t s2;
    cudaStreamCreateWithFlags(&s2, cudaStreamNonBlocking);
    cudaEvent_t eFork, eJoin;
    cudaEventCreateWithFlags(&eFork, cudaEventDisableTiming);
    cudaEventCreateWithFlags(&eJoin, cudaEventDisableTiming);

    cudaEventRecord(eFork, 0);
    cudaStreamWaitEvent(s2, eFork, 0);

    cudaMemsetAsync(deg, 0, (size_t)NT * sizeof(int), s2);
    k_deg<<<(EPT + ETA + 255) / 256, 256, 0, s2>>>(src_pt, dst_pt, src_ta, dst_ta);
    k_alloc<<<(NT + 255) / 256, 256, 0, s2>>>();
    k_fill<<<(EPT + ETA + 255) / 256, 256, 0, s2>>>(src_pt, dst_pt, src_ta, dst_ta);
    k_embed2<<<((NPL + NAR) * 32 + 255) / 256, 256, 0, s2>>>(pl_ids, ar_ids, pl_table,
                                                             ar_table, type_tab, xh, xl);
    cudaEventRecord(eJoin, s2);

    // main: encode GEMM (fp32 source path) -> x planes (track region)
    k_mma<128, false, false, false, false, true><<<GRID, 512, SMEM_K128>>>(
        track_x, nullptr, nullptr, nullptr, nullptr,
        Wtr, nullptr, btr, type_tab + H,
        nullptr, nullptr, nullptr, nullptr,
        xh + (size_t)OFF_TR * H, xl + (size_t)OFF_TR * H, nullptr, NTR);

    cudaStreamWaitEvent(0, eJoin, 0);

    // ---- layer 0 ----
    k_gather<<<(NT + 7) / 8, 256>>>(xh, xl, ah, al);
    k_mma<256, true, true, false, false, false><<<GRID, 512, SMEM_K256>>>(
        nullptr, ah, al, xh, xl,
        Wl0, Wr0, bl0, nullptr,
        nullptr, nullptr, nullptr, nullptr,
        yh, yl, nullptr, NT);

    // ---- layer 1 ----
    k_gather<<<(NT + 7) / 8, 256>>>(yh, yl, ah, al);
    k_mma<256, true, true, false, false, false><<<GRID, 512, SMEM_K256>>>(
        nullptr, ah, al, yh, yl,
        Wl1, Wr1, bl1, nullptr,
        nullptr, nullptr, nullptr, nullptr,
        xh, xl, nullptr, NT);

    // ---- predictor (gather + GEMM + dot fused) ----
    k_mma<256, false, true, true, true, false><<<GRID, 512, SMEM_K256>>>(
        nullptr, nullptr, nullptr, xh, xl,
        Wp1, nullptr, bp1, nullptr,
        lab_row, lab_col, Wp2, bp2,
        nullptr, nullptr, out, LBL);
}